// round 1
// baseline (speedup 1.0000x reference)
#include <cuda_runtime.h>
#include <math.h>

// Problem constants (fixed shapes from reference)
#define B_   16
#define S_   4096
#define D_   1024
#define M_   (B_ * S_)      // 65536 rows of the big GEMM
#define NBC_ 8              // number of column blocks in GEMM (1024 / 128)

// ---------------- device scratch (no allocations allowed) ----------------
__device__ float g_dec_feat[B_ * D_];            // [b][e]
__device__ float g_score_part[NBC_ * M_];        // [col_block][b*S+s]
__device__ float g_ctx_part[8 * B_ * D_];        // [s_chunk][b][d]

// ---------------- kernel 1: dec_feat[b,e] = dec[b,:]·W_s[e,:] + b_s[e] ----
__global__ void dec_feat_kernel(const float* __restrict__ dec,
                                const float* __restrict__ Ws,
                                const float* __restrict__ bs) {
    const int e = blockIdx.x & (D_ - 1);
    const int b = blockIdx.x >> 10;
    const float* wrow = Ws + (size_t)e * D_;
    const float* drow = dec + (size_t)b * D_;
    float a = 0.f;
    for (int d = threadIdx.x; d < D_; d += 128) a += wrow[d] * drow[d];
    // block reduce (128 threads = 4 warps)
    #pragma unroll
    for (int off = 16; off > 0; off >>= 1)
        a += __shfl_down_sync(0xffffffffu, a, off);
    __shared__ float sred[4];
    const int lane = threadIdx.x & 31, w = threadIdx.x >> 5;
    if (lane == 0) sred[w] = a;
    __syncthreads();
    if (threadIdx.x == 0) {
        float t = sred[0] + sred[1] + sred[2] + sred[3];
        g_dec_feat[b * D_ + e] = t + bs[e];
    }
}

// ---------------- kernel 2: fused GEMM + tanh + v-dot -> score partials ---
// C[m, e] = A[m,:]·Wh[e,:]   (A = encoder [M,1024], Wh row-major [1024,1024])
// partial_score[by][m] = sum_{e in block-cols} v[e]*tanh(C + df + cov*wc)
__global__ __launch_bounds__(256, 2)
void score_gemm_kernel(const float* __restrict__ A,
                       const float* __restrict__ Wh,
                       const float* __restrict__ coverage,
                       const float* __restrict__ w_c,
                       const float* __restrict__ v) {
    __shared__ float As[8][128];
    __shared__ float Bs[8][128];

    const int tid  = threadIdx.x;
    const int row0 = blockIdx.x * 128;
    const int col0 = blockIdx.y * 128;
    const int tn = tid & 15;       // 0..15 (column group)
    const int tm = tid >> 4;       // 0..15 (row group)

    const int lrow = tid >> 1;     // 0..127, tile row to load
    const int lk4  = (tid & 1) * 4;

    float acc[8][8];
    #pragma unroll
    for (int i = 0; i < 8; i++)
        #pragma unroll
        for (int j = 0; j < 8; j++) acc[i][j] = 0.f;

    const float* Arow = A  + (size_t)(row0 + lrow) * D_ + lk4;
    const float* Brow = Wh + (size_t)(col0 + lrow) * D_ + lk4;

    for (int k0 = 0; k0 < D_; k0 += 8) {
        float4 av = *(const float4*)(Arow + k0);
        float4 bv = *(const float4*)(Brow + k0);
        As[lk4 + 0][lrow] = av.x; As[lk4 + 1][lrow] = av.y;
        As[lk4 + 2][lrow] = av.z; As[lk4 + 3][lrow] = av.w;
        Bs[lk4 + 0][lrow] = bv.x; Bs[lk4 + 1][lrow] = bv.y;
        Bs[lk4 + 2][lrow] = bv.z; Bs[lk4 + 3][lrow] = bv.w;
        __syncthreads();
        #pragma unroll
        for (int kk = 0; kk < 8; kk++) {
            float4 a0 = *(const float4*)&As[kk][tm * 4];
            float4 a1 = *(const float4*)&As[kk][64 + tm * 4];
            float4 b0 = *(const float4*)&Bs[kk][tn * 4];
            float4 b1 = *(const float4*)&Bs[kk][64 + tn * 4];
            float ar[8] = {a0.x, a0.y, a0.z, a0.w, a1.x, a1.y, a1.z, a1.w};
            float br[8] = {b0.x, b0.y, b0.z, b0.w, b1.x, b1.y, b1.z, b1.w};
            #pragma unroll
            for (int i = 0; i < 8; i++)
                #pragma unroll
                for (int j = 0; j < 8; j++)
                    acc[i][j] += ar[i] * br[j];
        }
        __syncthreads();
    }

    // -------- fused epilogue --------
    const int b_idx = row0 >> 12;   // row0 / 4096 (tile never crosses a batch)
    const float* df = g_dec_feat + b_idx * D_;

    int R[8], C[8];
    #pragma unroll
    for (int i = 0; i < 4; i++) {
        R[i]     = row0 + tm * 4 + i;
        R[i + 4] = row0 + 64 + tm * 4 + i;
        C[i]     = col0 + tn * 4 + i;
        C[i + 4] = col0 + 64 + tn * 4 + i;
    }
    float dfv[8], wcv[8], vv[8], cvr[8];
    #pragma unroll
    for (int j = 0; j < 8; j++) {
        dfv[j] = df[C[j]];
        wcv[j] = w_c[C[j]];
        vv[j]  = v[C[j]];
    }
    #pragma unroll
    for (int i = 0; i < 8; i++) cvr[i] = coverage[R[i]];

    float part[8];
    #pragma unroll
    for (int i = 0; i < 8; i++) {
        float p = 0.f;
        #pragma unroll
        for (int j = 0; j < 8; j++)
            p += vv[j] * tanhf(acc[i][j] + dfv[j] + cvr[i] * wcv[j]);
        part[i] = p;
    }
    // reduce across the 16 column-thread groups (width-16 shuffle segments)
    #pragma unroll
    for (int off = 8; off > 0; off >>= 1)
        #pragma unroll
        for (int i = 0; i < 8; i++)
            part[i] += __shfl_down_sync(0xffffffffu, part[i], off, 16);

    if (tn == 0) {
        float* dst = g_score_part + (size_t)blockIdx.y * M_;
        #pragma unroll
        for (int i = 0; i < 8; i++) dst[R[i]] = part[i];
    }
}

// ---------------- kernel 3: softmax + mask renorm + coverage ----------------
__device__ __forceinline__ float block_reduce_1024(float val, bool is_max) {
    __shared__ float sh[32];
    __syncthreads();  // protect sh reuse across calls
    const int lane = threadIdx.x & 31, wid = threadIdx.x >> 5;
    #pragma unroll
    for (int off = 16; off > 0; off >>= 1) {
        float o = __shfl_down_sync(0xffffffffu, val, off);
        val = is_max ? fmaxf(val, o) : (val + o);
    }
    if (lane == 0) sh[wid] = val;
    __syncthreads();
    if (wid == 0) {
        val = sh[lane];
        #pragma unroll
        for (int off = 16; off > 0; off >>= 1) {
            float o = __shfl_down_sync(0xffffffffu, val, off);
            val = is_max ? fmaxf(val, o) : (val + o);
        }
        if (lane == 0) sh[0] = val;
    }
    __syncthreads();
    return sh[0];
}

__global__ __launch_bounds__(1024)
void softmax_kernel(const float* __restrict__ mask,
                    const float* __restrict__ coverage,
                    float* __restrict__ attn_out,
                    float* __restrict__ cov_out) {
    const int b = blockIdx.x;
    const int tid = threadIdx.x;

    float sc[4];
    #pragma unroll
    for (int i = 0; i < 4; i++) {
        const int idx = b * S_ + tid + i * 1024;
        float t = 0.f;
        #pragma unroll
        for (int p = 0; p < NBC_; p++) t += g_score_part[p * M_ + idx];
        sc[i] = t;
    }
    float mx = fmaxf(fmaxf(sc[0], sc[1]), fmaxf(sc[2], sc[3]));
    mx = block_reduce_1024(mx, true);

    float e[4], lsum = 0.f;
    #pragma unroll
    for (int i = 0; i < 4; i++) { e[i] = expf(sc[i] - mx); lsum += e[i]; }
    const float tot = block_reduce_1024(lsum, false);

    float p[4], lsum2 = 0.f;
    #pragma unroll
    for (int i = 0; i < 4; i++) {
        const int s = tid + i * 1024;
        p[i] = (e[i] / tot) * mask[b * S_ + s];
        lsum2 += p[i];
    }
    const float tot2 = block_reduce_1024(lsum2, false);

    #pragma unroll
    for (int i = 0; i < 4; i++) {
        const int s = tid + i * 1024;
        const float a = p[i] / tot2;
        attn_out[b * S_ + s] = a;
        cov_out[b * S_ + s]  = coverage[b * S_ + s] + a;
    }
}

// ---------------- kernel 4: context partials over s-chunks ----------------
__global__ __launch_bounds__(256)
void ctx_part_kernel(const float* __restrict__ enc,
                     const float* __restrict__ attn) {
    const int b  = blockIdx.x;
    const int d  = blockIdx.y * 256 + threadIdx.x;
    const int s0 = blockIdx.z * 512;
    const float* ep = enc + ((size_t)b * S_ + s0) * D_ + d;
    const float* ap = attn + b * S_ + s0;
    float acc = 0.f;
    #pragma unroll 8
    for (int s = 0; s < 512; s++)
        acc += ap[s] * ep[(size_t)s * D_];
    g_ctx_part[((size_t)blockIdx.z * B_ + b) * D_ + d] = acc;
}

// ---------------- kernel 5: reduce context partials -> output -------------
__global__ void ctx_reduce_kernel(float* __restrict__ ctx_out) {
    const int idx = blockIdx.x * 256 + threadIdx.x;  // < 16384
    float a = 0.f;
    #pragma unroll
    for (int p = 0; p < 8; p++) a += g_ctx_part[p * (B_ * D_) + idx];
    ctx_out[idx] = a;
}

// ---------------- launcher ----------------
extern "C" void kernel_launch(void* const* d_in, const int* in_sizes, int n_in,
                              void* d_out, int out_size) {
    const float* enc  = (const float*)d_in[0];  // [16,4096,1024]
    const float* dec  = (const float*)d_in[1];  // [16,1,1024]
    const float* mask = (const float*)d_in[2];  // [16,4096]
    const float* cov  = (const float*)d_in[3];  // [16,4096]
    const float* Wh   = (const float*)d_in[4];  // [1024,1024]
    const float* Ws   = (const float*)d_in[5];  // [1024,1024]
    const float* bs   = (const float*)d_in[6];  // [1024]
    const float* wc   = (const float*)d_in[7];  // [1024]
    const float* v    = (const float*)d_in[8];  // [1024]

    float* out  = (float*)d_out;
    float* ctx  = out;                       // [16,1024]
    float* attn = out + B_ * D_;             // [16,4096]
    float* covn = attn + B_ * S_;            // [16,4096]

    dec_feat_kernel<<<B_ * D_, 128>>>(dec, Ws, bs);
    score_gemm_kernel<<<dim3(M_ / 128, NBC_), 256>>>(enc, Wh, cov, wc, v);
    softmax_kernel<<<B_, 1024>>>(mask, cov, attn, covn);
    ctx_part_kernel<<<dim3(B_, 4, 8), 256>>>(enc, attn);
    ctx_reduce_kernel<<<64, 256>>>(ctx);
}

// round 3
// speedup vs baseline: 3.5039x; 3.5039x over previous
#include <cuda_runtime.h>
#include <math.h>
#include <stdint.h>

// Problem constants
#define B_   16
#define S_   4096
#define D_   1024
#define M_   (B_ * S_)
#define NBC_ 8               // n partial blocks (1024 / 128)

// ---------------- device scratch ----------------
__device__ float g_dec_feat[B_ * D_];
__device__ float g_score_part[NBC_ * M_];
__device__ float g_ctx_part[32 * B_ * D_];

// ================= PTX helpers (plain sm_100-safe) =================
__device__ __forceinline__ uint32_t smem_u32(const void* p) {
    uint32_t a;
    asm("{ .reg .u64 t; cvta.to.shared.u64 t, %1; cvt.u32.u64 %0, t; }" : "=r"(a) : "l"(p));
    return a;
}

#define CP_ASYNC16(dst, src) \
    asm volatile("cp.async.cg.shared.global [%0], [%1], 16;" :: "r"(dst), "l"(src) : "memory")
#define CP_COMMIT() asm volatile("cp.async.commit_group;" ::: "memory")
#define CP_WAIT1()  asm volatile("cp.async.wait_group 1;" ::: "memory")

#define LDSM4(r, addr) \
    asm volatile("ldmatrix.sync.aligned.m8n8.x4.shared.b16 {%0,%1,%2,%3}, [%4];" \
        : "=r"((r)[0]), "=r"((r)[1]), "=r"((r)[2]), "=r"((r)[3]) : "r"(addr))

#define MMA_TF32(c, a, b0v, b1v) \
    asm volatile("mma.sync.aligned.m16n8k8.row.col.f32.tf32.tf32.f32 " \
        "{%0,%1,%2,%3}, {%4,%5,%6,%7}, {%8,%9}, {%0,%1,%2,%3};" \
        : "+f"((c)[0]), "+f"((c)[1]), "+f"((c)[2]), "+f"((c)[3]) \
        : "r"((a)[0]), "r"((a)[1]), "r"((a)[2]), "r"((a)[3]), "r"(b0v), "r"(b1v))

__device__ __forceinline__ uint32_t f2tf32(uint32_t x) {
    uint32_t r;
    asm("cvt.rna.tf32.f32 %0, %1;" : "=r"(r) : "f"(__uint_as_float(x)));
    return r;
}

// ================= score GEMM (mma.sync tf32, cp.async pipeline) =================
#define BM   128
#define BN   128
#define BK   32
#define STG  3
#define NKT  (D_ / BK)              // 32
#define SA_OFF(s) ((s) * 16384)                 // A stages: 3 * 16KB
#define SB_OFF(s) (49152 + (s) * 16384)         // B stages: 3 * 16KB
#define OFF_DF  98304
#define OFF_WC  (OFF_DF + 512)
#define OFF_V   (OFF_WC + 512)
#define OFF_SBF (OFF_V + 512)                   // 128*4 floats = 2048B
#define SMEM_DYN (OFF_SBF + 2048)

__global__ __launch_bounds__(256, 2)
void score_gemm_kernel(const float* __restrict__ A,     // encoder [M,1024]
                       const float* __restrict__ Wh,    // [1024,1024]
                       const float* __restrict__ coverage,
                       const float* __restrict__ w_c,
                       const float* __restrict__ v) {
    extern __shared__ __align__(128) char smem[];
    const uint32_t sb = smem_u32(smem);
    const int tid = threadIdx.x, lane = tid & 31, wid = tid >> 5;
    const int wm = wid >> 2, wn = wid & 3;      // 2 x 4 warp grid
    const int n0 = blockIdx.x * BN;
    const int m0 = blockIdx.y * BM;

    // epilogue per-column vectors (region disjoint from stages)
    if (tid < 128) {
        const int e = n0 + tid;
        ((float*)(smem + OFF_DF))[tid] = g_dec_feat[(m0 >> 12) * D_ + e];
        ((float*)(smem + OFF_WC))[tid] = w_c[e];
        ((float*)(smem + OFF_V))[tid]  = v[e];
    }

    // ldmatrix per-lane geometry
    const int a_rowb = wm * 64 + (lane & 15);          // + mt*16
    const int a_c16  = lane >> 4;
    const int b_rowb = wn * 32 + ((lane >> 4) << 3) + (lane & 7);  // + p*16
    const int b_c16  = (lane >> 3) & 1;

    float acc[4][4][4];
    #pragma unroll
    for (int i = 0; i < 4; i++)
        #pragma unroll
        for (int j = 0; j < 4; j++)
            #pragma unroll
            for (int k = 0; k < 4; k++) acc[i][j][k] = 0.f;

    // stage loader: 4 cp.async for A + 4 for B per thread (32KB/stage)
    auto load_stage = [&](int st, int kt) {
        #pragma unroll
        for (int it = 0; it < 4; it++) {
            const int idx = tid + it * 256;            // 0..1023
            const int row = idx >> 3, cb = idx & 7;
            const float* srcA = A + (size_t)(m0 + row) * D_ + kt * BK + cb * 4;
            const uint32_t dstA = sb + SA_OFF(st) + row * 128 + ((cb ^ (row & 7)) << 4);
            CP_ASYNC16(dstA, srcA);
        }
        #pragma unroll
        for (int it = 0; it < 4; it++) {
            const int idx = tid + it * 256;
            const int row = idx >> 3, cb = idx & 7;
            const float* srcB = Wh + (size_t)(n0 + row) * D_ + kt * BK + cb * 4;
            const uint32_t dstB = sb + SB_OFF(st) + row * 128 + ((cb ^ (row & 7)) << 4);
            CP_ASYNC16(dstB, srcB);
        }
    };

    // prologue: stages 0,1
    load_stage(0, 0); CP_COMMIT();
    load_stage(1, 1); CP_COMMIT();

    for (int kt = 0; kt < NKT; kt++) {
        CP_WAIT1();
        __syncthreads();
        const int st = kt % STG;
        const uint32_t aB = sb + SA_OFF(st);
        const uint32_t bB = sb + SB_OFF(st);

        #pragma unroll
        for (int ks = 0; ks < 4; ks++) {
            uint32_t af[4][4], bf[2][4];
            #pragma unroll
            for (int mt = 0; mt < 4; mt++) {
                const int row = a_rowb + mt * 16;
                const uint32_t ad = aB + row * 128 + ((((ks << 1) | a_c16) ^ (row & 7)) << 4);
                LDSM4(af[mt], ad);
            }
            #pragma unroll
            for (int p = 0; p < 2; p++) {
                const int row = b_rowb + p * 16;
                const uint32_t bd = bB + row * 128 + ((((ks << 1) | b_c16) ^ (row & 7)) << 4);
                LDSM4(bf[p], bd);
            }
            #pragma unroll
            for (int mt = 0; mt < 4; mt++)
                #pragma unroll
                for (int i = 0; i < 4; i++) af[mt][i] = f2tf32(af[mt][i]);
            #pragma unroll
            for (int p = 0; p < 2; p++)
                #pragma unroll
                for (int i = 0; i < 4; i++) bf[p][i] = f2tf32(bf[p][i]);

            #pragma unroll
            for (int mt = 0; mt < 4; mt++)
                #pragma unroll
                for (int nt = 0; nt < 4; nt++)
                    MMA_TF32(acc[mt][nt], af[mt],
                             bf[nt >> 1][(nt & 1) * 2], bf[nt >> 1][(nt & 1) * 2 + 1]);
        }
        if (kt + 2 < NKT) load_stage((kt + 2) % STG, kt + 2);
        CP_COMMIT();
    }
    __syncthreads();

    // -------- fused epilogue: tanh + v-dot, reduce to per-row partial --------
    const float* sdf = (const float*)(smem + OFF_DF);
    const float* swc = (const float*)(smem + OFF_WC);
    const float* sv  = (const float*)(smem + OFF_V);
    float* sbuf = (float*)(smem + OFF_SBF);

    const int g = lane >> 2, tig = lane & 3;
    #pragma unroll
    for (int mt = 0; mt < 4; mt++) {
        #pragma unroll
        for (int h = 0; h < 2; h++) {
            const int rl = wm * 64 + mt * 16 + h * 8 + g;
            const float cov = coverage[m0 + rl];
            float part = 0.f;
            #pragma unroll
            for (int nt = 0; nt < 4; nt++) {
                #pragma unroll
                for (int q = 0; q < 2; q++) {
                    const int cl = wn * 32 + nt * 8 + tig * 2 + q;
                    float x = acc[mt][nt][h * 2 + q] + sdf[cl] + cov * swc[cl];
                    x = fminf(fmaxf(x, -10.f), 10.f);
                    const float t = __expf(2.f * x);
                    part = fmaf(sv[cl], __fdividef(t - 1.f, t + 1.f), part);
                }
            }
            part += __shfl_down_sync(0xffffffffu, part, 1, 4);
            part += __shfl_down_sync(0xffffffffu, part, 2, 4);
            if (tig == 0) sbuf[rl * 4 + wn] = part;
        }
    }
    __syncthreads();
    if (tid < 128) {
        const float s = sbuf[tid * 4] + sbuf[tid * 4 + 1]
                      + sbuf[tid * 4 + 2] + sbuf[tid * 4 + 3];
        g_score_part[(size_t)blockIdx.x * M_ + m0 + tid] = s;
    }
}

// ================= kernel 1: dec_feat =================
__global__ void dec_feat_kernel(const float* __restrict__ dec,
                                const float* __restrict__ Ws,
                                const float* __restrict__ bs) {
    const int e = blockIdx.x & (D_ - 1);
    const int b = blockIdx.x >> 10;
    const float* wrow = Ws + (size_t)e * D_;
    const float* drow = dec + (size_t)b * D_;
    float a = 0.f;
    for (int d = threadIdx.x; d < D_; d += 128) a += wrow[d] * drow[d];
    #pragma unroll
    for (int off = 16; off > 0; off >>= 1)
        a += __shfl_down_sync(0xffffffffu, a, off);
    __shared__ float sred[4];
    const int lane = threadIdx.x & 31, w = threadIdx.x >> 5;
    if (lane == 0) sred[w] = a;
    __syncthreads();
    if (threadIdx.x == 0) {
        float t = sred[0] + sred[1] + sred[2] + sred[3];
        g_dec_feat[b * D_ + e] = t + bs[e];
    }
}

// ================= kernel 3: softmax =================
__device__ __forceinline__ float block_reduce_1024(float val, bool is_max) {
    __shared__ float sh[32];
    __syncthreads();
    const int lane = threadIdx.x & 31, wid = threadIdx.x >> 5;
    #pragma unroll
    for (int off = 16; off > 0; off >>= 1) {
        float o = __shfl_down_sync(0xffffffffu, val, off);
        val = is_max ? fmaxf(val, o) : (val + o);
    }
    if (lane == 0) sh[wid] = val;
    __syncthreads();
    if (wid == 0) {
        val = sh[lane];
        #pragma unroll
        for (int off = 16; off > 0; off >>= 1) {
            float o = __shfl_down_sync(0xffffffffu, val, off);
            val = is_max ? fmaxf(val, o) : (val + o);
        }
        if (lane == 0) sh[0] = val;
    }
    __syncthreads();
    return sh[0];
}

__global__ __launch_bounds__(1024)
void softmax_kernel(const float* __restrict__ mask,
                    const float* __restrict__ coverage,
                    float* __restrict__ attn_out,
                    float* __restrict__ cov_out) {
    const int b = blockIdx.x;
    const int tid = threadIdx.x;

    float sc[4];
    #pragma unroll
    for (int i = 0; i < 4; i++) {
        const int idx = b * S_ + tid + i * 1024;
        float t = 0.f;
        #pragma unroll
        for (int p = 0; p < NBC_; p++) t += g_score_part[(size_t)p * M_ + idx];
        sc[i] = t;
    }
    float mx = fmaxf(fmaxf(sc[0], sc[1]), fmaxf(sc[2], sc[3]));
    mx = block_reduce_1024(mx, true);

    float e[4], lsum = 0.f;
    #pragma unroll
    for (int i = 0; i < 4; i++) { e[i] = expf(sc[i] - mx); lsum += e[i]; }
    const float tot = block_reduce_1024(lsum, false);

    float p[4], lsum2 = 0.f;
    #pragma unroll
    for (int i = 0; i < 4; i++) {
        const int s = tid + i * 1024;
        p[i] = (e[i] / tot) * mask[b * S_ + s];
        lsum2 += p[i];
    }
    const float tot2 = block_reduce_1024(lsum2, false);

    #pragma unroll
    for (int i = 0; i < 4; i++) {
        const int s = tid + i * 1024;
        const float a = p[i] / tot2;
        attn_out[b * S_ + s] = a;
        cov_out[b * S_ + s]  = coverage[b * S_ + s] + a;
    }
}

// ================= kernel 4/5: context =================
__global__ __launch_bounds__(256)
void ctx_part_kernel(const float* __restrict__ enc,
                     const float* __restrict__ attn) {
    const int b  = blockIdx.x;
    const int sc = blockIdx.y;            // 0..31
    const int s0 = sc * 128;
    const float4* ep = (const float4*)(enc + ((size_t)b * S_ + s0) * D_) + threadIdx.x;
    const float* ap = attn + b * S_ + s0;
    float4 acc = {0.f, 0.f, 0.f, 0.f};
    #pragma unroll 4
    for (int s = 0; s < 128; s++) {
        const float a = ap[s];
        const float4 e = ep[(size_t)s * 256];
        acc.x = fmaf(a, e.x, acc.x);
        acc.y = fmaf(a, e.y, acc.y);
        acc.z = fmaf(a, e.z, acc.z);
        acc.w = fmaf(a, e.w, acc.w);
    }
    ((float4*)(g_ctx_part + ((size_t)sc * B_ + b) * D_))[threadIdx.x] = acc;
}

__global__ void ctx_reduce_kernel(float* __restrict__ ctx_out) {
    const int idx = blockIdx.x * 256 + threadIdx.x;   // < 16384
    float a = 0.f;
    #pragma unroll
    for (int p = 0; p < 32; p++) a += g_ctx_part[(size_t)p * (B_ * D_) + idx];
    ctx_out[idx] = a;
}

// ================= launcher =================
extern "C" void kernel_launch(void* const* d_in, const int* in_sizes, int n_in,
                              void* d_out, int out_size) {
    const float* enc  = (const float*)d_in[0];
    const float* dec  = (const float*)d_in[1];
    const float* mask = (const float*)d_in[2];
    const float* cov  = (const float*)d_in[3];
    const float* Wh   = (const float*)d_in[4];
    const float* Ws   = (const float*)d_in[5];
    const float* bs   = (const float*)d_in[6];
    const float* wc   = (const float*)d_in[7];
    const float* v    = (const float*)d_in[8];

    float* out  = (float*)d_out;
    float* ctx  = out;
    float* attn = out + B_ * D_;
    float* covn = attn + B_ * S_;

    static bool attr_set = false;
    if (!attr_set) {
        cudaFuncSetAttribute(score_gemm_kernel,
                             cudaFuncAttributeMaxDynamicSharedMemorySize, SMEM_DYN);
        attr_set = true;
    }

    dec_feat_kernel<<<B_ * D_, 128>>>(dec, Ws, bs);
    score_gemm_kernel<<<dim3(D_ / BN, M_ / BM), 256, SMEM_DYN>>>(enc, Wh, cov, wc, v);
    softmax_kernel<<<B_, 1024>>>(mask, cov, attn, covn);
    ctx_part_kernel<<<dim3(B_, 32), 256>>>(enc, attn);
    ctx_reduce_kernel<<<64, 256>>>(ctx);
}

// round 4
// speedup vs baseline: 6.4484x; 1.8404x over previous
#include <cuda_runtime.h>
#include <cuda_fp16.h>
#include <math.h>
#include <stdint.h>

// Problem constants
#define B_   16
#define S_   4096
#define D_   1024
#define M_   (B_ * S_)
#define NBC_ 8               // n partial blocks (1024 / 128)

// ---------------- device scratch ----------------
__device__ float g_dec_feat[B_ * D_];
__device__ float g_score_part[NBC_ * M_];
__device__ float g_ctx_part[32 * B_ * D_];
__device__ __align__(16) __half g_enc_h[(size_t)M_ * D_];   // fp16 mirror of encoder
__device__ __align__(16) __half g_wh_h[(size_t)D_ * D_];    // fp16 mirror of W_h

// ================= PTX helpers (plain sm_100-safe) =================
__device__ __forceinline__ uint32_t smem_u32(const void* p) {
    uint32_t a;
    asm("{ .reg .u64 t; cvta.to.shared.u64 t, %1; cvt.u32.u64 %0, t; }" : "=r"(a) : "l"(p));
    return a;
}

#define CP_ASYNC16(dst, src) \
    asm volatile("cp.async.cg.shared.global [%0], [%1], 16;" :: "r"(dst), "l"(src) : "memory")
#define CP_COMMIT() asm volatile("cp.async.commit_group;" ::: "memory")
#define CP_WAIT1()  asm volatile("cp.async.wait_group 1;" ::: "memory")

#define LDSM4(r, addr) \
    asm volatile("ldmatrix.sync.aligned.m8n8.x4.shared.b16 {%0,%1,%2,%3}, [%4];" \
        : "=r"((r)[0]), "=r"((r)[1]), "=r"((r)[2]), "=r"((r)[3]) : "r"(addr))

#define MMA_F16(c, a, b0v, b1v) \
    asm volatile("mma.sync.aligned.m16n8k16.row.col.f32.f16.f16.f32 " \
        "{%0,%1,%2,%3}, {%4,%5,%6,%7}, {%8,%9}, {%0,%1,%2,%3};" \
        : "+f"((c)[0]), "+f"((c)[1]), "+f"((c)[2]), "+f"((c)[3]) \
        : "r"((a)[0]), "r"((a)[1]), "r"((a)[2]), "r"((a)[3]), "r"(b0v), "r"(b1v))

// ================= convert f32 -> f16 =================
__global__ __launch_bounds__(256)
void f32_to_f16_kernel(const float* __restrict__ src, __half* __restrict__ dst,
                       int n4) {
    const int stride = gridDim.x * 256;
    for (int i = blockIdx.x * 256 + threadIdx.x; i < n4; i += stride) {
        const float4 v = ((const float4*)src)[i];
        __half2* d = (__half2*)dst + (size_t)i * 2;
        d[0] = __floats2half2_rn(v.x, v.y);
        d[1] = __floats2half2_rn(v.z, v.w);
    }
}

// ================= score GEMM (mma.sync f16, cp.async pipeline) =================
// C[m,n] = enc_h[m,:] . wh_h[n,:]  (both K-contiguous fp16 rows, 128B per BK=64)
#define BM   128
#define BN   128
#define BK   64                     // fp16 elems = 128 bytes = SW128 atom row
#define STG  3
#define NKT  (D_ / BK)              // 16
#define SA_OFF(s) ((s) * 16384)                 // A stages: 3 * 16KB
#define SB_OFF(s) (49152 + (s) * 16384)         // B stages: 3 * 16KB
#define OFF_DF  98304
#define OFF_WC  (OFF_DF + 512)
#define OFF_V   (OFF_WC + 512)
#define OFF_SBF (OFF_V + 512)                   // 128*4 floats = 2048B
#define SMEM_DYN (OFF_SBF + 2048)

__global__ __launch_bounds__(256, 2)
void score_gemm_kernel(const float* __restrict__ coverage,
                       const float* __restrict__ w_c,
                       const float* __restrict__ v) {
    extern __shared__ __align__(128) char smem[];
    const uint32_t sb = smem_u32(smem);
    const int tid = threadIdx.x, lane = tid & 31, wid = tid >> 5;
    const int wm = wid >> 2, wn = wid & 3;      // 2 x 4 warp grid
    const int n0 = blockIdx.x * BN;
    const int m0 = blockIdx.y * BM;

    const __half* A  = g_enc_h;
    const __half* Bw = g_wh_h;

    if (tid < 128) {
        const int e = n0 + tid;
        ((float*)(smem + OFF_DF))[tid] = g_dec_feat[(m0 >> 12) * D_ + e];
        ((float*)(smem + OFF_WC))[tid] = w_c[e];
        ((float*)(smem + OFF_V))[tid]  = v[e];
    }

    // ldmatrix per-lane geometry
    const int a_rowb = wm * 64 + (lane & 15);                       // + mt*16
    const int a_cofs = lane >> 4;                                   // chunk +0/+1
    const int b_rowb = wn * 32 + ((lane >> 4) << 3) + (lane & 7);   // + p*16
    const int b_cofs = (lane >> 3) & 1;

    float acc[4][4][4];
    #pragma unroll
    for (int i = 0; i < 4; i++)
        #pragma unroll
        for (int j = 0; j < 4; j++)
            #pragma unroll
            for (int k = 0; k < 4; k++) acc[i][j][k] = 0.f;

    // stage loader: 4 cp.async for A + 4 for B per thread (16KB+16KB per stage)
    auto load_stage = [&](int st, int kt) {
        #pragma unroll
        for (int it = 0; it < 4; it++) {
            const int idx = tid + it * 256;            // 0..1023 chunks
            const int row = idx >> 3, cb = idx & 7;
            const __half* srcA = A + (size_t)(m0 + row) * D_ + kt * BK + cb * 8;
            const uint32_t dstA = sb + SA_OFF(st) + row * 128 + ((cb ^ (row & 7)) << 4);
            CP_ASYNC16(dstA, srcA);
        }
        #pragma unroll
        for (int it = 0; it < 4; it++) {
            const int idx = tid + it * 256;
            const int row = idx >> 3, cb = idx & 7;
            const __half* srcB = Bw + (size_t)(n0 + row) * D_ + kt * BK + cb * 8;
            const uint32_t dstB = sb + SB_OFF(st) + row * 128 + ((cb ^ (row & 7)) << 4);
            CP_ASYNC16(dstB, srcB);
        }
    };

    load_stage(0, 0); CP_COMMIT();
    load_stage(1, 1); CP_COMMIT();

    for (int kt = 0; kt < NKT; kt++) {
        CP_WAIT1();
        __syncthreads();
        const int st = kt % STG;
        const uint32_t aB = sb + SA_OFF(st);
        const uint32_t bB = sb + SB_OFF(st);

        #pragma unroll
        for (int ks = 0; ks < 4; ks++) {     // 4 x k16 per BK=64
            uint32_t af[4][4], bf[2][4];
            #pragma unroll
            for (int mt = 0; mt < 4; mt++) {
                const int row = a_rowb + mt * 16;
                const int ch  = 2 * ks + a_cofs;
                const uint32_t ad = aB + row * 128 + ((ch ^ (row & 7)) << 4);
                LDSM4(af[mt], ad);
            }
            #pragma unroll
            for (int p = 0; p < 2; p++) {
                const int row = b_rowb + p * 16;
                const int ch  = 2 * ks + b_cofs;
                const uint32_t bd = bB + row * 128 + ((ch ^ (row & 7)) << 4);
                LDSM4(bf[p], bd);
            }
            #pragma unroll
            for (int mt = 0; mt < 4; mt++)
                #pragma unroll
                for (int nt = 0; nt < 4; nt++)
                    MMA_F16(acc[mt][nt], af[mt],
                            bf[nt >> 1][(nt & 1) * 2], bf[nt >> 1][(nt & 1) * 2 + 1]);
        }
        if (kt + 2 < NKT) load_stage((kt + 2) % STG, kt + 2);
        CP_COMMIT();
    }
    __syncthreads();

    // -------- fused epilogue: tanh + v-dot -> per-row partial --------
    const float* sdf = (const float*)(smem + OFF_DF);
    const float* swc = (const float*)(smem + OFF_WC);
    const float* sv  = (const float*)(smem + OFF_V);
    float* sbuf = (float*)(smem + OFF_SBF);

    const int g = lane >> 2, tig = lane & 3;
    #pragma unroll
    for (int mt = 0; mt < 4; mt++) {
        #pragma unroll
        for (int h = 0; h < 2; h++) {
            const int rl = wm * 64 + mt * 16 + h * 8 + g;
            const float cov = coverage[m0 + rl];
            float part = 0.f;
            #pragma unroll
            for (int nt = 0; nt < 4; nt++) {
                #pragma unroll
                for (int q = 0; q < 2; q++) {
                    const int cl = wn * 32 + nt * 8 + tig * 2 + q;
                    float x = acc[mt][nt][h * 2 + q] + sdf[cl] + cov * swc[cl];
                    x = fminf(fmaxf(x, -10.f), 10.f);
                    const float t = __expf(2.f * x);
                    part = fmaf(sv[cl], __fdividef(t - 1.f, t + 1.f), part);
                }
            }
            part += __shfl_down_sync(0xffffffffu, part, 1, 4);
            part += __shfl_down_sync(0xffffffffu, part, 2, 4);
            if (tig == 0) sbuf[rl * 4 + wn] = part;
        }
    }
    __syncthreads();
    if (tid < 128) {
        const float s = sbuf[tid * 4] + sbuf[tid * 4 + 1]
                      + sbuf[tid * 4 + 2] + sbuf[tid * 4 + 3];
        g_score_part[(size_t)blockIdx.x * M_ + m0 + tid] = s;
    }
}

// ================= kernel 1: dec_feat =================
__global__ void dec_feat_kernel(const float* __restrict__ dec,
                                const float* __restrict__ Ws,
                                const float* __restrict__ bs) {
    const int e = blockIdx.x & (D_ - 1);
    const int b = blockIdx.x >> 10;
    const float* wrow = Ws + (size_t)e * D_;
    const float* drow = dec + (size_t)b * D_;
    float a = 0.f;
    for (int d = threadIdx.x; d < D_; d += 128) a += wrow[d] * drow[d];
    #pragma unroll
    for (int off = 16; off > 0; off >>= 1)
        a += __shfl_down_sync(0xffffffffu, a, off);
    __shared__ float sred[4];
    const int lane = threadIdx.x & 31, w = threadIdx.x >> 5;
    if (lane == 0) sred[w] = a;
    __syncthreads();
    if (threadIdx.x == 0) {
        float t = sred[0] + sred[1] + sred[2] + sred[3];
        g_dec_feat[b * D_ + e] = t + bs[e];
    }
}

// ================= kernel 3: softmax =================
__device__ __forceinline__ float block_reduce_1024(float val, bool is_max) {
    __shared__ float sh[32];
    __syncthreads();
    const int lane = threadIdx.x & 31, wid = threadIdx.x >> 5;
    #pragma unroll
    for (int off = 16; off > 0; off >>= 1) {
        float o = __shfl_down_sync(0xffffffffu, val, off);
        val = is_max ? fmaxf(val, o) : (val + o);
    }
    if (lane == 0) sh[wid] = val;
    __syncthreads();
    if (wid == 0) {
        val = sh[lane];
        #pragma unroll
        for (int off = 16; off > 0; off >>= 1) {
            float o = __shfl_down_sync(0xffffffffu, val, off);
            val = is_max ? fmaxf(val, o) : (val + o);
        }
        if (lane == 0) sh[0] = val;
    }
    __syncthreads();
    return sh[0];
}

__global__ __launch_bounds__(1024)
void softmax_kernel(const float* __restrict__ mask,
                    const float* __restrict__ coverage,
                    float* __restrict__ attn_out,
                    float* __restrict__ cov_out) {
    const int b = blockIdx.x;
    const int tid = threadIdx.x;

    float sc[4];
    #pragma unroll
    for (int i = 0; i < 4; i++) {
        const int idx = b * S_ + tid + i * 1024;
        float t = 0.f;
        #pragma unroll
        for (int p = 0; p < NBC_; p++) t += g_score_part[(size_t)p * M_ + idx];
        sc[i] = t;
    }
    float mx = fmaxf(fmaxf(sc[0], sc[1]), fmaxf(sc[2], sc[3]));
    mx = block_reduce_1024(mx, true);

    float e[4], lsum = 0.f;
    #pragma unroll
    for (int i = 0; i < 4; i++) { e[i] = expf(sc[i] - mx); lsum += e[i]; }
    const float tot = block_reduce_1024(lsum, false);

    float p[4], lsum2 = 0.f;
    #pragma unroll
    for (int i = 0; i < 4; i++) {
        const int s = tid + i * 1024;
        p[i] = (e[i] / tot) * mask[b * S_ + s];
        lsum2 += p[i];
    }
    const float tot2 = block_reduce_1024(lsum2, false);

    #pragma unroll
    for (int i = 0; i < 4; i++) {
        const int s = tid + i * 1024;
        const float a = p[i] / tot2;
        attn_out[b * S_ + s] = a;
        cov_out[b * S_ + s]  = coverage[b * S_ + s] + a;
    }
}

// ================= kernel 4/5: context =================
__global__ __launch_bounds__(256)
void ctx_part_kernel(const float* __restrict__ enc,
                     const float* __restrict__ attn) {
    const int b  = blockIdx.x;
    const int sc = blockIdx.y;            // 0..31
    const int s0 = sc * 128;
    const float4* ep = (const float4*)(enc + ((size_t)b * S_ + s0) * D_) + threadIdx.x;
    const float* ap = attn + b * S_ + s0;
    float4 acc = {0.f, 0.f, 0.f, 0.f};
    #pragma unroll 4
    for (int s = 0; s < 128; s++) {
        const float a = ap[s];
        const float4 e = ep[(size_t)s * 256];
        acc.x = fmaf(a, e.x, acc.x);
        acc.y = fmaf(a, e.y, acc.y);
        acc.z = fmaf(a, e.z, acc.z);
        acc.w = fmaf(a, e.w, acc.w);
    }
    ((float4*)(g_ctx_part + ((size_t)sc * B_ + b) * D_))[threadIdx.x] = acc;
}

__global__ void ctx_reduce_kernel(float* __restrict__ ctx_out) {
    const int idx = blockIdx.x * 256 + threadIdx.x;   // < 16384
    float a = 0.f;
    #pragma unroll
    for (int p = 0; p < 32; p++) a += g_ctx_part[(size_t)p * (B_ * D_) + idx];
    ctx_out[idx] = a;
}

// ================= launcher =================
extern "C" void kernel_launch(void* const* d_in, const int* in_sizes, int n_in,
                              void* d_out, int out_size) {
    const float* enc  = (const float*)d_in[0];
    const float* dec  = (const float*)d_in[1];
    const float* mask = (const float*)d_in[2];
    const float* cov  = (const float*)d_in[3];
    const float* Wh   = (const float*)d_in[4];
    const float* Ws   = (const float*)d_in[5];
    const float* bs   = (const float*)d_in[6];
    const float* wc   = (const float*)d_in[7];
    const float* v    = (const float*)d_in[8];

    float* out  = (float*)d_out;
    float* ctx  = out;
    float* attn = out + B_ * D_;
    float* covn = attn + B_ * S_;

    static bool attr_set = false;
    if (!attr_set) {
        cudaFuncSetAttribute(score_gemm_kernel,
                             cudaFuncAttributeMaxDynamicSharedMemorySize, SMEM_DYN);
        attr_set = true;
    }

    __half* enc_h = nullptr; __half* wh_h = nullptr;
    cudaGetSymbolAddress((void**)&enc_h, g_enc_h);
    cudaGetSymbolAddress((void**)&wh_h, g_wh_h);

    f32_to_f16_kernel<<<4096, 256>>>(enc, enc_h, (M_ / 4) * D_);
    f32_to_f16_kernel<<<1024, 256>>>(Wh, wh_h, (D_ / 4) * D_);
    dec_feat_kernel<<<B_ * D_, 128>>>(dec, Ws, bs);
    score_gemm_kernel<<<dim3(D_ / BN, M_ / BM), 256, SMEM_DYN>>>(cov, wc, v);
    softmax_kernel<<<B_, 1024>>>(mask, cov, attn, covn);
    ctx_part_kernel<<<dim3(B_, 32), 256>>>(enc, attn);
    ctx_reduce_kernel<<<64, 256>>>(ctx);
}

// round 5
// speedup vs baseline: 6.6275x; 1.0278x over previous
#include <cuda_runtime.h>
#include <cuda_fp16.h>
#include <math.h>
#include <stdint.h>

// Problem constants
#define B_   16
#define S_   4096
#define D_   1024
#define M_   (B_ * S_)
#define NBC_ 8               // n partial blocks (1024 / 128)

// ---------------- device scratch ----------------
__device__ float g_dec_feat[B_ * D_];
__device__ float g_score_part[NBC_ * M_];
__device__ float g_ctx_part[32 * B_ * D_];
__device__ __align__(16) __half g_enc_h[(size_t)M_ * D_];   // fp16 mirror of encoder
__device__ __align__(16) __half g_wh_h[(size_t)D_ * D_];    // fp16 mirror of W_h

// ================= PTX helpers (plain sm_100-safe) =================
__device__ __forceinline__ uint32_t smem_u32(const void* p) {
    uint32_t a;
    asm("{ .reg .u64 t; cvta.to.shared.u64 t, %1; cvt.u32.u64 %0, t; }" : "=r"(a) : "l"(p));
    return a;
}

#define CP_ASYNC16(dst, src) \
    asm volatile("cp.async.cg.shared.global [%0], [%1], 16;" :: "r"(dst), "l"(src) : "memory")
#define CP_COMMIT() asm volatile("cp.async.commit_group;" ::: "memory")
#define CP_WAIT1()  asm volatile("cp.async.wait_group 1;" ::: "memory")

#define LDSM4(r, addr) \
    asm volatile("ldmatrix.sync.aligned.m8n8.x4.shared.b16 {%0,%1,%2,%3}, [%4];" \
        : "=r"((r)[0]), "=r"((r)[1]), "=r"((r)[2]), "=r"((r)[3]) : "r"(addr))

#define MMA_F16(c, a, b0v, b1v) \
    asm volatile("mma.sync.aligned.m16n8k16.row.col.f32.f16.f16.f32 " \
        "{%0,%1,%2,%3}, {%4,%5,%6,%7}, {%8,%9}, {%0,%1,%2,%3};" \
        : "+f"((c)[0]), "+f"((c)[1]), "+f"((c)[2]), "+f"((c)[3]) \
        : "r"((a)[0]), "r"((a)[1]), "r"((a)[2]), "r"((a)[3]), "r"(b0v), "r"(b1v))

// ================= convert f32 -> f16 =================
__global__ __launch_bounds__(256)
void f32_to_f16_kernel(const float* __restrict__ src, __half* __restrict__ dst,
                       int n4) {
    const int stride = gridDim.x * 256;
    for (int i = blockIdx.x * 256 + threadIdx.x; i < n4; i += stride) {
        const float4 v = ((const float4*)src)[i];
        __half2* d = (__half2*)dst + (size_t)i * 2;
        d[0] = __floats2half2_rn(v.x, v.y);
        d[1] = __floats2half2_rn(v.z, v.w);
    }
}

// ================= score GEMM (mma.sync f16, cp.async + frag pipeline) =======
#define BM   128
#define BN   128
#define BK   64                     // fp16 elems = 128 bytes = SW128 atom row
#define STG  3
#define NKT  (D_ / BK)              // 16
#define SA_OFF(s) ((s) * 16384)
#define SB_OFF(s) (49152 + (s) * 16384)
#define OFF_DF  98304
#define OFF_WC  (OFF_DF + 512)
#define OFF_V   (OFF_WC + 512)
#define OFF_SBF (OFF_V + 512)
#define SMEM_DYN (OFF_SBF + 2048)

__global__ __launch_bounds__(256, 2)
void score_gemm_kernel(const float* __restrict__ coverage,
                       const float* __restrict__ w_c,
                       const float* __restrict__ v) {
    extern __shared__ __align__(128) char smem[];
    const uint32_t sb = smem_u32(smem);
    const int tid = threadIdx.x, lane = tid & 31, wid = tid >> 5;
    const int wm = wid >> 2, wn = wid & 3;      // 2 x 4 warp grid
    const int n0 = blockIdx.x * BN;
    const int m0 = blockIdx.y * BM;

    const __half* A  = g_enc_h;
    const __half* Bw = g_wh_h;

    if (tid < 128) {
        const int e = n0 + tid;
        ((float*)(smem + OFF_DF))[tid] = g_dec_feat[(m0 >> 12) * D_ + e];
        ((float*)(smem + OFF_WC))[tid] = w_c[e];
        ((float*)(smem + OFF_V))[tid]  = v[e];
    }

    // ldmatrix per-lane geometry
    const int a_rowb = wm * 64 + (lane & 15);                       // + mt*16
    const int a_cofs = lane >> 4;                                   // chunk +0/+1
    const int b_rowb = wn * 32 + ((lane >> 4) << 3) + (lane & 7);   // + p*16
    const int b_cofs = (lane >> 3) & 1;

    float acc[4][4][4];
    #pragma unroll
    for (int i = 0; i < 4; i++)
        #pragma unroll
        for (int j = 0; j < 4; j++)
            #pragma unroll
            for (int k = 0; k < 4; k++) acc[i][j][k] = 0.f;

    auto load_stage = [&](int st, int kt) {
        #pragma unroll
        for (int it = 0; it < 4; it++) {
            const int idx = tid + it * 256;
            const int row = idx >> 3, cb = idx & 7;
            const __half* srcA = A + (size_t)(m0 + row) * D_ + kt * BK + cb * 8;
            const uint32_t dstA = sb + SA_OFF(st) + row * 128 + ((cb ^ (row & 7)) << 4);
            CP_ASYNC16(dstA, srcA);
        }
        #pragma unroll
        for (int it = 0; it < 4; it++) {
            const int idx = tid + it * 256;
            const int row = idx >> 3, cb = idx & 7;
            const __half* srcB = Bw + (size_t)(n0 + row) * D_ + kt * BK + cb * 8;
            const uint32_t dstB = sb + SB_OFF(st) + row * 128 + ((cb ^ (row & 7)) << 4);
            CP_ASYNC16(dstB, srcB);
        }
    };

    load_stage(0, 0); CP_COMMIT();
    load_stage(1, 1); CP_COMMIT();

    uint32_t afb[2][4][4], bfb[2][2][4];

    auto ldsm_step = [&](uint32_t aB, uint32_t bB, int ks, int buf) {
        #pragma unroll
        for (int mt = 0; mt < 4; mt++) {
            const int row = a_rowb + mt * 16;
            const int ch  = 2 * ks + a_cofs;
            LDSM4(afb[buf][mt], aB + row * 128 + ((ch ^ (row & 7)) << 4));
        }
        #pragma unroll
        for (int p = 0; p < 2; p++) {
            const int row = b_rowb + p * 16;
            const int ch  = 2 * ks + b_cofs;
            LDSM4(bfb[buf][p], bB + row * 128 + ((ch ^ (row & 7)) << 4));
        }
    };

    for (int kt = 0; kt < NKT; kt++) {
        CP_WAIT1();
        __syncthreads();
        // issue next-stage copies immediately (stage (kt+2)%3 was consumed at kt-1)
        if (kt + 2 < NKT) load_stage((kt + 2) % STG, kt + 2);
        CP_COMMIT();

        const int st = kt % STG;
        const uint32_t aB = sb + SA_OFF(st);
        const uint32_t bB = sb + SB_OFF(st);

        ldsm_step(aB, bB, 0, 0);
        #pragma unroll
        for (int ks = 0; ks < 4; ks++) {
            const int cur = ks & 1, nxt = cur ^ 1;
            if (ks < 3) ldsm_step(aB, bB, ks + 1, nxt);
            #pragma unroll
            for (int mt = 0; mt < 4; mt++)
                #pragma unroll
                for (int nt = 0; nt < 4; nt++)
                    MMA_F16(acc[mt][nt], afb[cur][mt],
                            bfb[cur][nt >> 1][(nt & 1) * 2],
                            bfb[cur][nt >> 1][(nt & 1) * 2 + 1]);
        }
    }
    __syncthreads();

    // -------- fused epilogue: tanh + v-dot -> per-row partial --------
    const float* sdf = (const float*)(smem + OFF_DF);
    const float* swc = (const float*)(smem + OFF_WC);
    const float* sv  = (const float*)(smem + OFF_V);
    float* sbuf = (float*)(smem + OFF_SBF);

    const int g = lane >> 2, tig = lane & 3;
    #pragma unroll
    for (int mt = 0; mt < 4; mt++) {
        #pragma unroll
        for (int h = 0; h < 2; h++) {
            const int rl = wm * 64 + mt * 16 + h * 8 + g;
            const float cov = coverage[m0 + rl];
            float part = 0.f;
            #pragma unroll
            for (int nt = 0; nt < 4; nt++) {
                #pragma unroll
                for (int q = 0; q < 2; q++) {
                    const int cl = wn * 32 + nt * 8 + tig * 2 + q;
                    float x = acc[mt][nt][h * 2 + q] + sdf[cl] + cov * swc[cl];
                    x = fminf(fmaxf(x, -10.f), 10.f);
                    const float t = __expf(2.f * x);
                    part = fmaf(sv[cl], __fdividef(t - 1.f, t + 1.f), part);
                }
            }
            part += __shfl_down_sync(0xffffffffu, part, 1, 4);
            part += __shfl_down_sync(0xffffffffu, part, 2, 4);
            if (tig == 0) sbuf[rl * 4 + wn] = part;
        }
    }
    __syncthreads();
    if (tid < 128) {
        const float s = sbuf[tid * 4] + sbuf[tid * 4 + 1]
                      + sbuf[tid * 4 + 2] + sbuf[tid * 4 + 3];
        g_score_part[(size_t)blockIdx.x * M_ + m0 + tid] = s;
    }
}

// ================= kernel 1: dec_feat =================
__global__ void dec_feat_kernel(const float* __restrict__ dec,
                                const float* __restrict__ Ws,
                                const float* __restrict__ bs) {
    const int e = blockIdx.x & (D_ - 1);
    const int b = blockIdx.x >> 10;
    const float* wrow = Ws + (size_t)e * D_;
    const float* drow = dec + (size_t)b * D_;
    float a = 0.f;
    for (int d = threadIdx.x; d < D_; d += 128) a += wrow[d] * drow[d];
    #pragma unroll
    for (int off = 16; off > 0; off >>= 1)
        a += __shfl_down_sync(0xffffffffu, a, off);
    __shared__ float sred[4];
    const int lane = threadIdx.x & 31, w = threadIdx.x >> 5;
    if (lane == 0) sred[w] = a;
    __syncthreads();
    if (threadIdx.x == 0) {
        float t = sred[0] + sred[1] + sred[2] + sred[3];
        g_dec_feat[b * D_ + e] = t + bs[e];
    }
}

// ================= kernel 3: softmax =================
__device__ __forceinline__ float block_reduce_1024(float val, bool is_max) {
    __shared__ float sh[32];
    __syncthreads();
    const int lane = threadIdx.x & 31, wid = threadIdx.x >> 5;
    #pragma unroll
    for (int off = 16; off > 0; off >>= 1) {
        float o = __shfl_down_sync(0xffffffffu, val, off);
        val = is_max ? fmaxf(val, o) : (val + o);
    }
    if (lane == 0) sh[wid] = val;
    __syncthreads();
    if (wid == 0) {
        val = sh[lane];
        #pragma unroll
        for (int off = 16; off > 0; off >>= 1) {
            float o = __shfl_down_sync(0xffffffffu, val, off);
            val = is_max ? fmaxf(val, o) : (val + o);
        }
        if (lane == 0) sh[0] = val;
    }
    __syncthreads();
    return sh[0];
}

__global__ __launch_bounds__(1024)
void softmax_kernel(const float* __restrict__ mask,
                    const float* __restrict__ coverage,
                    float* __restrict__ attn_out,
                    float* __restrict__ cov_out) {
    const int b = blockIdx.x;
    const int tid = threadIdx.x;

    float sc[4];
    #pragma unroll
    for (int i = 0; i < 4; i++) {
        const int idx = b * S_ + tid + i * 1024;
        float t = 0.f;
        #pragma unroll
        for (int p = 0; p < NBC_; p++) t += g_score_part[(size_t)p * M_ + idx];
        sc[i] = t;
    }
    float mx = fmaxf(fmaxf(sc[0], sc[1]), fmaxf(sc[2], sc[3]));
    mx = block_reduce_1024(mx, true);

    float e[4], lsum = 0.f;
    #pragma unroll
    for (int i = 0; i < 4; i++) { e[i] = expf(sc[i] - mx); lsum += e[i]; }
    const float tot = block_reduce_1024(lsum, false);

    float p[4], lsum2 = 0.f;
    #pragma unroll
    for (int i = 0; i < 4; i++) {
        const int s = tid + i * 1024;
        p[i] = (e[i] / tot) * mask[b * S_ + s];
        lsum2 += p[i];
    }
    const float tot2 = block_reduce_1024(lsum2, false);

    #pragma unroll
    for (int i = 0; i < 4; i++) {
        const int s = tid + i * 1024;
        const float a = p[i] / tot2;
        attn_out[b * S_ + s] = a;
        cov_out[b * S_ + s]  = coverage[b * S_ + s] + a;
    }
}

// ================= kernel 4/5: context (fp16 encoder mirror) =================
__global__ __launch_bounds__(256)
void ctx_part_kernel(const float* __restrict__ attn) {
    const int b  = blockIdx.x;
    const int sc = blockIdx.y;            // 0..31
    const int s0 = sc * 128;
    // each thread covers 4 consecutive d (8 bytes of fp16)
    const uint2* ep = (const uint2*)(g_enc_h + ((size_t)b * S_ + s0) * D_) + threadIdx.x;
    const float* ap = attn + b * S_ + s0;
    float ax = 0.f, ay = 0.f, az = 0.f, aw = 0.f;
    #pragma unroll 4
    for (int s = 0; s < 128; s++) {
        const float a = ap[s];
        const uint2 e8 = ep[(size_t)s * 256];
        const float2 e0 = __half22float2(*(const __half2*)&e8.x);
        const float2 e1 = __half22float2(*(const __half2*)&e8.y);
        ax = fmaf(a, e0.x, ax);
        ay = fmaf(a, e0.y, ay);
        az = fmaf(a, e1.x, az);
        aw = fmaf(a, e1.y, aw);
    }
    float4 r = {ax, ay, az, aw};
    ((float4*)(g_ctx_part + ((size_t)sc * B_ + b) * D_))[threadIdx.x] = r;
}

__global__ void ctx_reduce_kernel(float* __restrict__ ctx_out) {
    const int idx = blockIdx.x * 256 + threadIdx.x;   // < 16384
    float a = 0.f;
    #pragma unroll
    for (int p = 0; p < 32; p++) a += g_ctx_part[(size_t)p * (B_ * D_) + idx];
    ctx_out[idx] = a;
}

// ================= launcher =================
extern "C" void kernel_launch(void* const* d_in, const int* in_sizes, int n_in,
                              void* d_out, int out_size) {
    const float* enc  = (const float*)d_in[0];
    const float* dec  = (const float*)d_in[1];
    const float* mask = (const float*)d_in[2];
    const float* cov  = (const float*)d_in[3];
    const float* Wh   = (const float*)d_in[4];
    const float* Ws   = (const float*)d_in[5];
    const float* bs   = (const float*)d_in[6];
    const float* wc   = (const float*)d_in[7];
    const float* v    = (const float*)d_in[8];

    float* out  = (float*)d_out;
    float* ctx  = out;
    float* attn = out + B_ * D_;
    float* covn = attn + B_ * S_;

    static bool attr_set = false;
    if (!attr_set) {
        cudaFuncSetAttribute(score_gemm_kernel,
                             cudaFuncAttributeMaxDynamicSharedMemorySize, SMEM_DYN);
        attr_set = true;
    }

    __half* enc_h = nullptr; __half* wh_h = nullptr;
    cudaGetSymbolAddress((void**)&enc_h, g_enc_h);
    cudaGetSymbolAddress((void**)&wh_h, g_wh_h);

    f32_to_f16_kernel<<<4096, 256>>>(enc, enc_h, (M_ / 4) * D_);
    f32_to_f16_kernel<<<1024, 256>>>(Wh, wh_h, (D_ / 4) * D_);
    dec_feat_kernel<<<B_ * D_, 128>>>(dec, Ws, bs);
    score_gemm_kernel<<<dim3(D_ / BN, M_ / BM), 256, SMEM_DYN>>>(cov, wc, v);
    softmax_kernel<<<B_, 1024>>>(mask, cov, attn, covn);
    ctx_part_kernel<<<dim3(B_, 32), 256>>>(attn);
    ctx_reduce_kernel<<<64, 256>>>(ctx);
}

// round 6
// speedup vs baseline: 7.1373x; 1.0769x over previous
#include <cuda_runtime.h>
#include <cuda_fp16.h>
#include <math.h>
#include <stdint.h>

// Problem constants
#define B_   16
#define S_   4096
#define D_   1024
#define M_   (B_ * S_)
#define NBC_ 8               // n partial blocks (1024 / 128)

// ---------------- device scratch ----------------
__device__ float g_dec_feat[B_ * D_];
__device__ float g_score_part[NBC_ * M_];
__device__ float g_ctx_part[32 * B_ * D_];
__device__ __align__(16) __half g_enc_h[(size_t)M_ * D_];   // fp16 mirror of encoder
__device__ __align__(16) __half g_wh_h[(size_t)D_ * D_];    // fp16 mirror of W_h

// ================= PTX helpers (plain sm_100-safe) =================
__device__ __forceinline__ uint32_t smem_u32(const void* p) {
    uint32_t a;
    asm("{ .reg .u64 t; cvta.to.shared.u64 t, %1; cvt.u32.u64 %0, t; }" : "=r"(a) : "l"(p));
    return a;
}

#define CP_ASYNC16(dst, src) \
    asm volatile("cp.async.cg.shared.global [%0], [%1], 16;" :: "r"(dst), "l"(src) : "memory")
#define CP_COMMIT() asm volatile("cp.async.commit_group;" ::: "memory")
#define CP_WAIT1()  asm volatile("cp.async.wait_group 1;" ::: "memory")

#define LDSM4(r, addr) \
    asm volatile("ldmatrix.sync.aligned.m8n8.x4.shared.b16 {%0,%1,%2,%3}, [%4];" \
        : "=r"((r)[0]), "=r"((r)[1]), "=r"((r)[2]), "=r"((r)[3]) : "r"(addr))

#define MMA_F16(c, a, b0v, b1v) \
    asm volatile("mma.sync.aligned.m16n8k16.row.col.f32.f16.f16.f32 " \
        "{%0,%1,%2,%3}, {%4,%5,%6,%7}, {%8,%9}, {%0,%1,%2,%3};" \
        : "+f"((c)[0]), "+f"((c)[1]), "+f"((c)[2]), "+f"((c)[3]) \
        : "r"((a)[0]), "r"((a)[1]), "r"((a)[2]), "r"((a)[3]), "r"(b0v), "r"(b1v))

__device__ __forceinline__ float fast_tanh(float x) {
    float r;
    asm("tanh.approx.f32 %0, %1;" : "=f"(r) : "f"(x));
    return r;
}

// ================= convert f32 -> f16 =================
__global__ __launch_bounds__(256)
void f32_to_f16_kernel(const float* __restrict__ src, __half* __restrict__ dst,
                       int n4) {
    const int stride = gridDim.x * 256;
    for (int i = blockIdx.x * 256 + threadIdx.x; i < n4; i += stride) {
        const float4 v = ((const float4*)src)[i];
        __half2* d = (__half2*)dst + (size_t)i * 2;
        d[0] = __floats2half2_rn(v.x, v.y);
        d[1] = __floats2half2_rn(v.z, v.w);
    }
}

// ================= score GEMM (mma.sync f16, cp.async pipeline) =================
#define BM   128
#define BN   128
#define BK   64                     // fp16 elems = 128 bytes = SW128 atom row
#define STG  3
#define NKT  (D_ / BK)              // 16
#define SA_OFF(s) ((s) * 16384)
#define SB_OFF(s) (49152 + (s) * 16384)
#define OFF_DF  98304
#define OFF_WC  (OFF_DF + 512)
#define OFF_V   (OFF_WC + 512)
#define OFF_CV  (OFF_V + 512)
#define OFF_SBF (OFF_CV + 512)
#define SMEM_DYN (OFF_SBF + 2048)

__global__ __launch_bounds__(256, 2)
void score_gemm_kernel(const float* __restrict__ coverage,
                       const float* __restrict__ w_c,
                       const float* __restrict__ v) {
    extern __shared__ __align__(128) char smem[];
    const uint32_t sb = smem_u32(smem);
    const int tid = threadIdx.x, lane = tid & 31, wid = tid >> 5;
    const int wm = wid >> 2, wn = wid & 3;      // 2 x 4 warp grid
    const int n0 = blockIdx.x * BN;
    const int m0 = blockIdx.y * BM;

    const __half* A  = g_enc_h;
    const __half* Bw = g_wh_h;

    if (tid < 128) {
        const int e = n0 + tid;
        ((float*)(smem + OFF_DF))[tid] = g_dec_feat[(m0 >> 12) * D_ + e];
        ((float*)(smem + OFF_WC))[tid] = w_c[e];
        ((float*)(smem + OFF_V))[tid]  = v[e];
        ((float*)(smem + OFF_CV))[tid] = coverage[m0 + tid];
    }

    // ldmatrix per-lane geometry
    const int a_rowb = wm * 64 + (lane & 15);                       // + mt*16
    const int a_cofs = lane >> 4;
    const int b_rowb = wn * 32 + ((lane >> 4) << 3) + (lane & 7);   // + p*16
    const int b_cofs = (lane >> 3) & 1;

    float acc[4][4][4];
    #pragma unroll
    for (int i = 0; i < 4; i++)
        #pragma unroll
        for (int j = 0; j < 4; j++)
            #pragma unroll
            for (int k = 0; k < 4; k++) acc[i][j][k] = 0.f;

    auto load_stage = [&](int st, int kt) {
        #pragma unroll
        for (int it = 0; it < 4; it++) {
            const int idx = tid + it * 256;
            const int row = idx >> 3, cb = idx & 7;
            const __half* srcA = A + (size_t)(m0 + row) * D_ + kt * BK + cb * 8;
            const uint32_t dstA = sb + SA_OFF(st) + row * 128 + ((cb ^ (row & 7)) << 4);
            CP_ASYNC16(dstA, srcA);
        }
        #pragma unroll
        for (int it = 0; it < 4; it++) {
            const int idx = tid + it * 256;
            const int row = idx >> 3, cb = idx & 7;
            const __half* srcB = Bw + (size_t)(n0 + row) * D_ + kt * BK + cb * 8;
            const uint32_t dstB = sb + SB_OFF(st) + row * 128 + ((cb ^ (row & 7)) << 4);
            CP_ASYNC16(dstB, srcB);
        }
    };

    load_stage(0, 0); CP_COMMIT();
    load_stage(1, 1); CP_COMMIT();

    for (int kt = 0; kt < NKT; kt++) {
        CP_WAIT1();
        __syncthreads();
        // issue next-stage copies now: stage (kt+2)%3 was fully consumed at kt-1
        if (kt + 2 < NKT) load_stage((kt + 2) % STG, kt + 2);
        CP_COMMIT();

        const int st = kt % STG;
        const uint32_t aB = sb + SA_OFF(st);
        const uint32_t bB = sb + SB_OFF(st);

        #pragma unroll
        for (int ks = 0; ks < 4; ks++) {     // 4 x k16 per BK=64
            uint32_t af[4][4], bf[2][4];
            #pragma unroll
            for (int mt = 0; mt < 4; mt++) {
                const int row = a_rowb + mt * 16;
                const int ch  = 2 * ks + a_cofs;
                LDSM4(af[mt], aB + row * 128 + ((ch ^ (row & 7)) << 4));
            }
            #pragma unroll
            for (int p = 0; p < 2; p++) {
                const int row = b_rowb + p * 16;
                const int ch  = 2 * ks + b_cofs;
                LDSM4(bf[p], bB + row * 128 + ((ch ^ (row & 7)) << 4));
            }
            #pragma unroll
            for (int mt = 0; mt < 4; mt++)
                #pragma unroll
                for (int nt = 0; nt < 4; nt++)
                    MMA_F16(acc[mt][nt], af[mt],
                            bf[nt >> 1][(nt & 1) * 2], bf[nt >> 1][(nt & 1) * 2 + 1]);
        }
    }
    __syncthreads();

    // -------- fused epilogue: tanh.approx + v-dot -> per-row partial --------
    const float* sdf  = (const float*)(smem + OFF_DF);
    const float* swc  = (const float*)(smem + OFF_WC);
    const float* sv   = (const float*)(smem + OFF_V);
    const float* scov = (const float*)(smem + OFF_CV);
    float* sbuf = (float*)(smem + OFF_SBF);

    const int g = lane >> 2, tig = lane & 3;
    #pragma unroll
    for (int mt = 0; mt < 4; mt++) {
        #pragma unroll
        for (int h = 0; h < 2; h++) {
            const int rl = wm * 64 + mt * 16 + h * 8 + g;
            const float cov = scov[rl];
            float part = 0.f;
            #pragma unroll
            for (int nt = 0; nt < 4; nt++) {
                #pragma unroll
                for (int q = 0; q < 2; q++) {
                    const int cl = wn * 32 + nt * 8 + tig * 2 + q;
                    const float x = acc[mt][nt][h * 2 + q] + sdf[cl] + cov * swc[cl];
                    part = fmaf(sv[cl], fast_tanh(x), part);
                }
            }
            part += __shfl_down_sync(0xffffffffu, part, 1, 4);
            part += __shfl_down_sync(0xffffffffu, part, 2, 4);
            if (tig == 0) sbuf[rl * 4 + wn] = part;
        }
    }
    __syncthreads();
    if (tid < 128) {
        const float s = sbuf[tid * 4] + sbuf[tid * 4 + 1]
                      + sbuf[tid * 4 + 2] + sbuf[tid * 4 + 3];
        g_score_part[(size_t)blockIdx.x * M_ + m0 + tid] = s;
    }
}

// ================= kernel 1: dec_feat (one block per e, all batches) =========
__global__ __launch_bounds__(128)
void dec_feat_kernel(const float* __restrict__ dec,
                     const float* __restrict__ Ws,
                     const float* __restrict__ bs) {
    const int e = blockIdx.x;           // 0..1023
    const int tid = threadIdx.x;
    const float* wrow = Ws + (size_t)e * D_;
    float w8[8];
    #pragma unroll
    for (int j = 0; j < 8; j++) w8[j] = wrow[j * 128 + tid];   // coalesced

    __shared__ float sred[4];
    const int lane = tid & 31, w = tid >> 5;
    const float be = bs[e];

    for (int b = 0; b < B_; b++) {
        const float* drow = dec + (size_t)b * D_;
        float a = 0.f;
        #pragma unroll
        for (int j = 0; j < 8; j++) a = fmaf(w8[j], drow[j * 128 + tid], a);
        #pragma unroll
        for (int off = 16; off > 0; off >>= 1)
            a += __shfl_down_sync(0xffffffffu, a, off);
        if (lane == 0) sred[w] = a;
        __syncthreads();
        if (tid == 0)
            g_dec_feat[b * D_ + e] = sred[0] + sred[1] + sred[2] + sred[3] + be;
        __syncthreads();
    }
}

// ================= kernel 3: softmax =================
__device__ __forceinline__ float block_reduce_1024(float val, bool is_max) {
    __shared__ float sh[32];
    __syncthreads();
    const int lane = threadIdx.x & 31, wid = threadIdx.x >> 5;
    #pragma unroll
    for (int off = 16; off > 0; off >>= 1) {
        float o = __shfl_down_sync(0xffffffffu, val, off);
        val = is_max ? fmaxf(val, o) : (val + o);
    }
    if (lane == 0) sh[wid] = val;
    __syncthreads();
    if (wid == 0) {
        val = sh[lane];
        #pragma unroll
        for (int off = 16; off > 0; off >>= 1) {
            float o = __shfl_down_sync(0xffffffffu, val, off);
            val = is_max ? fmaxf(val, o) : (val + o);
        }
        if (lane == 0) sh[0] = val;
    }
    __syncthreads();
    return sh[0];
}

__global__ __launch_bounds__(1024)
void softmax_kernel(const float* __restrict__ mask,
                    const float* __restrict__ coverage,
                    float* __restrict__ attn_out,
                    float* __restrict__ cov_out) {
    const int b = blockIdx.x;
    const int tid = threadIdx.x;

    float sc[4];
    #pragma unroll
    for (int i = 0; i < 4; i++) {
        const int idx = b * S_ + tid + i * 1024;
        float t = 0.f;
        #pragma unroll
        for (int p = 0; p < NBC_; p++) t += g_score_part[(size_t)p * M_ + idx];
        sc[i] = t;
    }
    float mx = fmaxf(fmaxf(sc[0], sc[1]), fmaxf(sc[2], sc[3]));
    mx = block_reduce_1024(mx, true);

    float e[4], lsum = 0.f;
    #pragma unroll
    for (int i = 0; i < 4; i++) { e[i] = expf(sc[i] - mx); lsum += e[i]; }
    const float tot = block_reduce_1024(lsum, false);

    float p[4], lsum2 = 0.f;
    #pragma unroll
    for (int i = 0; i < 4; i++) {
        const int s = tid + i * 1024;
        p[i] = (e[i] / tot) * mask[b * S_ + s];
        lsum2 += p[i];
    }
    const float tot2 = block_reduce_1024(lsum2, false);

    #pragma unroll
    for (int i = 0; i < 4; i++) {
        const int s = tid + i * 1024;
        const float a = p[i] / tot2;
        attn_out[b * S_ + s] = a;
        cov_out[b * S_ + s]  = coverage[b * S_ + s] + a;
    }
}

// ================= kernel 4/5: context (fp16 encoder mirror) =================
__global__ __launch_bounds__(256)
void ctx_part_kernel(const float* __restrict__ attn) {
    const int b  = blockIdx.x;
    const int sc = blockIdx.y;            // 0..31
    const int s0 = sc * 128;
    const uint2* ep = (const uint2*)(g_enc_h + ((size_t)b * S_ + s0) * D_) + threadIdx.x;
    const float* ap = attn + b * S_ + s0;
    float ax = 0.f, ay = 0.f, az = 0.f, aw = 0.f;
    #pragma unroll 4
    for (int s = 0; s < 128; s++) {
        const float a = ap[s];
        const uint2 e8 = ep[(size_t)s * 256];
        const float2 e0 = __half22float2(*(const __half2*)&e8.x);
        const float2 e1 = __half22float2(*(const __half2*)&e8.y);
        ax = fmaf(a, e0.x, ax);
        ay = fmaf(a, e0.y, ay);
        az = fmaf(a, e1.x, az);
        aw = fmaf(a, e1.y, aw);
    }
    float4 r = {ax, ay, az, aw};
    ((float4*)(g_ctx_part + ((size_t)sc * B_ + b) * D_))[threadIdx.x] = r;
}

__global__ void ctx_reduce_kernel(float* __restrict__ ctx_out) {
    const int idx = blockIdx.x * 256 + threadIdx.x;   // < 16384
    float a = 0.f;
    #pragma unroll
    for (int p = 0; p < 32; p++) a += g_ctx_part[(size_t)p * (B_ * D_) + idx];
    ctx_out[idx] = a;
}

// ================= launcher =================
extern "C" void kernel_launch(void* const* d_in, const int* in_sizes, int n_in,
                              void* d_out, int out_size) {
    const float* enc  = (const float*)d_in[0];
    const float* dec  = (const float*)d_in[1];
    const float* mask = (const float*)d_in[2];
    const float* cov  = (const float*)d_in[3];
    const float* Wh   = (const float*)d_in[4];
    const float* Ws   = (const float*)d_in[5];
    const float* bs   = (const float*)d_in[6];
    const float* wc   = (const float*)d_in[7];
    const float* v    = (const float*)d_in[8];

    float* out  = (float*)d_out;
    float* ctx  = out;
    float* attn = out + B_ * D_;
    float* covn = attn + B_ * S_;

    static bool attr_set = false;
    if (!attr_set) {
        cudaFuncSetAttribute(score_gemm_kernel,
                             cudaFuncAttributeMaxDynamicSharedMemorySize, SMEM_DYN);
        attr_set = true;
    }

    __half* enc_h = nullptr; __half* wh_h = nullptr;
    cudaGetSymbolAddress((void**)&enc_h, g_enc_h);
    cudaGetSymbolAddress((void**)&wh_h, g_wh_h);

    f32_to_f16_kernel<<<4096, 256>>>(enc, enc_h, (M_ / 4) * D_);
    f32_to_f16_kernel<<<1024, 256>>>(Wh, wh_h, (D_ / 4) * D_);
    dec_feat_kernel<<<D_, 128>>>(dec, Ws, bs);
    score_gemm_kernel<<<dim3(D_ / BN, M_ / BM), 256, SMEM_DYN>>>(cov, wc, v);
    softmax_kernel<<<B_, 1024>>>(mask, cov, attn, covn);
    ctx_part_kernel<<<dim3(B_, 32), 256>>>(attn);
    ctx_reduce_kernel<<<64, 256>>>(ctx);
}